// round 6
// baseline (speedup 1.0000x reference)
#include <cuda_runtime.h>

// LSTM2: 2-layer LSTM, B=1024, T=1024, H=64, input dim 1, output dim 1/step.
// Persistent-RNN: 128 CTAs x 512 threads, 8 batch rows per CTA.
// Thread = (hidden unit n, row-pair rp, k-half kh). Each thread accumulates
// gate dots over its 32-element k-half for 2 batch rows with f32x2 FMAs
// (weights reused across rows), then a 1-level shfl_xor butterfly merges the
// two k-halves; lane kh applies activations for row 2rp+kh (cell state in regs).
// Weights resident in SMEM, bank-conflict-free padded layout:
//   weight row pitch 72 floats, k-halves at +0 / +36
//   h      row pitch 76 floats, k-halves at +0 / +36

namespace {

constexpr int T_LEN = 1024;
constexpr int BATCH = 1024;
constexpr int RPC   = 8;             // batch rows per CTA
constexpr int NTH   = 512;           // threads per CTA
constexpr int GRID  = BATCH / RPC;   // 128

constexpr int WP    = 72;            // weight row pitch (floats)
constexpr int HP    = 76;            // h row pitch (floats)
constexpr int KHOFF = 36;            // offset of k-half 1 within a row
constexpr int HB    = RPC * HP;      // 608 floats per h buffer

// smem floats: 3 weight matrices (256x72) + w_lin(64) + h1,h2 double bufs + x staging
constexpr int SMEM_FLOATS = 3 * 256 * WP + 64 + 4 * HB + 16;
constexpr int SMEM_BYTES  = SMEM_FLOATS * 4;   // 231232 B  (< 232448 limit)

typedef unsigned long long u64;

__device__ __forceinline__ u64 fma2(u64 a, u64 b, u64 c) {
    u64 d;
    asm("fma.rn.f32x2 %0, %1, %2, %3;" : "=l"(d) : "l"(a), "l"(b), "l"(c));
    return d;
}
__device__ __forceinline__ float red2(u64 a) {
    return __uint_as_float((unsigned)a) + __uint_as_float((unsigned)(a >> 32));
}
__device__ __forceinline__ float sigm(float v) {
    return __fdividef(1.f, 1.f + __expf(-v));
}
__device__ __forceinline__ float tanh_(float v) {
    v = fminf(fmaxf(v, -15.f), 15.f);
    float e = __expf(-2.f * v);
    return __fdividef(1.f - e, 1.f + e);
}
// store position of hidden index k within a padded h row
__device__ __forceinline__ int hpos(int k) { return (k >> 5) * KHOFF + (k & 31); }

} // namespace

__global__ void __launch_bounds__(NTH, 1)
lstm2_kernel(const float* __restrict__ x,
             const float* __restrict__ w_ih1, const float* __restrict__ w_hh1,
             const float* __restrict__ b_ih1, const float* __restrict__ b_hh1,
             const float* __restrict__ w_ih2, const float* __restrict__ w_hh2,
             const float* __restrict__ b_ih2, const float* __restrict__ b_hh2,
             const float* __restrict__ w_lin, const float* __restrict__ b_lin,
             float* __restrict__ out)
{
    extern __shared__ float sm[];
    float* sWh1 = sm;                    // [256][72]
    float* sWi2 = sWh1 + 256 * WP;       // [256][72]
    float* sWh2 = sWi2 + 256 * WP;       // [256][72]
    float* sWl  = sWh2 + 256 * WP;       // [64]
    float* sH1  = sWl + 64;              // [2][8][76]
    float* sH2  = sH1 + 2 * HB;          // [2][8][76]
    float* sX   = sH2 + 2 * HB;          // [2][8]

    const int tid = threadIdx.x;
    const int rowbase = blockIdx.x * RPC;

    // ---- load weights into padded SMEM ----
    for (int i = tid; i < 256 * 64; i += NTH) {
        int j = i >> 6, k = i & 63;
        int off = j * WP + hpos(k);
        sWh1[off] = w_hh1[i];
        sWi2[off] = w_ih2[i];
        sWh2[off] = w_hh2[i];
    }
    if (tid < 64) sWl[tid] = w_lin[tid];
    for (int i = tid; i < 4 * HB; i += NTH) sH1[i] = 0.f;   // zeros h1 AND h2 (contiguous)
    if (tid < RPC) sX[tid] = x[(rowbase + tid) * T_LEN];
    __syncthreads();

    // thread mapping
    const int kh = tid & 1;            // k-half
    const int rp = (tid >> 1) & 3;     // row-pair
    const int n  = tid >> 3;           // hidden unit / gate group
    const int r0 = rp * 2;
    const int rsel = r0 + kh;          // the batch row this lane activates
    const int wid = tid >> 5, lid = tid & 31;
    const int khoff = kh * KHOFF;
    const int np = hpos(n);            // store position of unit n in an h row

    // per-thread constants from GMEM (once)
    const float b1i = b_ih1[n]       + b_hh1[n];
    const float b1f = b_ih1[n + 64]  + b_hh1[n + 64];
    const float b1g = b_ih1[n + 128] + b_hh1[n + 128];
    const float b1o = b_ih1[n + 192] + b_hh1[n + 192];
    const float b2i = b_ih2[n]       + b_hh2[n];
    const float b2f = b_ih2[n + 64]  + b_hh2[n + 64];
    const float b2g = b_ih2[n + 128] + b_hh2[n + 128];
    const float b2o = b_ih2[n + 192] + b_hh2[n + 192];
    const float wxi = w_ih1[n],       wxf = w_ih1[n + 64];
    const float wxg = w_ih1[n + 128], wxo = w_ih1[n + 192];
    const float blin = b_lin[0];

    // weight row pointers (this thread's k-half)
    const ulonglong2* Wi = (const ulonglong2*)(sWh1 + n * WP + khoff);
    const ulonglong2* Wf = (const ulonglong2*)(sWh1 + (n + 64) * WP + khoff);
    const ulonglong2* Wg = (const ulonglong2*)(sWh1 + (n + 128) * WP + khoff);
    const ulonglong2* Wo = (const ulonglong2*)(sWh1 + (n + 192) * WP + khoff);
    const ulonglong2* Ui = (const ulonglong2*)(sWi2 + n * WP + khoff);
    const ulonglong2* Uf = (const ulonglong2*)(sWi2 + (n + 64) * WP + khoff);
    const ulonglong2* Ug = (const ulonglong2*)(sWi2 + (n + 128) * WP + khoff);
    const ulonglong2* Uo = (const ulonglong2*)(sWi2 + (n + 192) * WP + khoff);
    const ulonglong2* Vi = (const ulonglong2*)(sWh2 + n * WP + khoff);
    const ulonglong2* Vf = (const ulonglong2*)(sWh2 + (n + 64) * WP + khoff);
    const ulonglong2* Vg = (const ulonglong2*)(sWh2 + (n + 128) * WP + khoff);
    const ulonglong2* Vo = (const ulonglong2*)(sWh2 + (n + 192) * WP + khoff);

    // persistent cell state for this lane's row
    float c1 = 0.f, c2 = 0.f;

    for (int t = 0; t < T_LEN; ++t) {
        const int p = t & 1, q = p ^ 1;

        // prefetch next x (hidden under compute)
        float xn = 0.f;
        if (tid < RPC) {
            int tn = (t + 1 < T_LEN) ? (t + 1) : t;
            xn = x[(rowbase + tid) * T_LEN + tn];
        }

        // ============ layer 1: partial gate dots over this k-half ============
        {
            const ulonglong2* Ha = (const ulonglong2*)(sH1 + p * HB + r0 * HP + khoff);
            const ulonglong2* Hb = (const ulonglong2*)(sH1 + p * HB + (r0 + 1) * HP + khoff);
            u64 ai0 = 0, af0 = 0, ag0 = 0, ao0 = 0;
            u64 ai1 = 0, af1 = 0, ag1 = 0, ao1 = 0;
            #pragma unroll
            for (int k = 0; k < 8; ++k) {
                ulonglong2 ha = Ha[k], hb = Hb[k];
                ulonglong2 wi = Wi[k], wf = Wf[k], wg = Wg[k], wo = Wo[k];
                ai0 = fma2(wi.x, ha.x, ai0); ai0 = fma2(wi.y, ha.y, ai0);
                af0 = fma2(wf.x, ha.x, af0); af0 = fma2(wf.y, ha.y, af0);
                ag0 = fma2(wg.x, ha.x, ag0); ag0 = fma2(wg.y, ha.y, ag0);
                ao0 = fma2(wo.x, ha.x, ao0); ao0 = fma2(wo.y, ha.y, ao0);
                ai1 = fma2(wi.x, hb.x, ai1); ai1 = fma2(wi.y, hb.y, ai1);
                af1 = fma2(wf.x, hb.x, af1); af1 = fma2(wf.y, hb.y, af1);
                ag1 = fma2(wg.x, hb.x, ag1); ag1 = fma2(wg.y, hb.y, ag1);
                ao1 = fma2(wo.x, hb.x, ao1); ao1 = fma2(wo.y, hb.y, ao1);
            }
            // merge k-halves (butterfly over lane bit 0)
            float ti0 = red2(ai0); ti0 += __shfl_xor_sync(~0u, ti0, 1);
            float tf0 = red2(af0); tf0 += __shfl_xor_sync(~0u, tf0, 1);
            float tg0 = red2(ag0); tg0 += __shfl_xor_sync(~0u, tg0, 1);
            float to0 = red2(ao0); to0 += __shfl_xor_sync(~0u, to0, 1);
            float ti1 = red2(ai1); ti1 += __shfl_xor_sync(~0u, ti1, 1);
            float tf1 = red2(af1); tf1 += __shfl_xor_sync(~0u, tf1, 1);
            float tg1 = red2(ag1); tg1 += __shfl_xor_sync(~0u, tg1, 1);
            float to1 = red2(ao1); to1 += __shfl_xor_sync(~0u, to1, 1);

            // lane kh activates row rsel = 2rp + kh
            const float xs = sX[p * RPC + rsel];
            float gi = fmaf(wxi, xs, b1i) + (kh ? ti1 : ti0);
            float gf = fmaf(wxf, xs, b1f) + (kh ? tf1 : tf0);
            float gg = fmaf(wxg, xs, b1g) + (kh ? tg1 : tg0);
            float go = fmaf(wxo, xs, b1o) + (kh ? to1 : to0);
            float ii = sigm(gi), ff = sigm(gf), gc = tanh_(gg), oo = sigm(go);
            c1 = ff * c1 + ii * gc;
            sH1[q * HB + rsel * HP + np] = oo * tanh_(c1);
        }
        if (tid < RPC) sX[q * RPC + tid] = xn;
        __syncthreads();   // h1[q] + x[q] published

        // ============ layer 2: over h1[q] (new) and h2[p] (old) ============
        {
            const ulonglong2* Pa = (const ulonglong2*)(sH1 + q * HB + r0 * HP + khoff);
            const ulonglong2* Pb = (const ulonglong2*)(sH1 + q * HB + (r0 + 1) * HP + khoff);
            const ulonglong2* Qa = (const ulonglong2*)(sH2 + p * HB + r0 * HP + khoff);
            const ulonglong2* Qb = (const ulonglong2*)(sH2 + p * HB + (r0 + 1) * HP + khoff);
            u64 ai0 = 0, af0 = 0, ag0 = 0, ao0 = 0;
            u64 ai1 = 0, af1 = 0, ag1 = 0, ao1 = 0;
            #pragma unroll
            for (int k = 0; k < 8; ++k) {
                ulonglong2 pa = Pa[k], pb = Pb[k];
                ulonglong2 ui = Ui[k], uf = Uf[k], ug = Ug[k], uo = Uo[k];
                ai0 = fma2(ui.x, pa.x, ai0); ai0 = fma2(ui.y, pa.y, ai0);
                af0 = fma2(uf.x, pa.x, af0); af0 = fma2(uf.y, pa.y, af0);
                ag0 = fma2(ug.x, pa.x, ag0); ag0 = fma2(ug.y, pa.y, ag0);
                ao0 = fma2(uo.x, pa.x, ao0); ao0 = fma2(uo.y, pa.y, ao0);
                ai1 = fma2(ui.x, pb.x, ai1); ai1 = fma2(ui.y, pb.y, ai1);
                af1 = fma2(uf.x, pb.x, af1); af1 = fma2(uf.y, pb.y, af1);
                ag1 = fma2(ug.x, pb.x, ag1); ag1 = fma2(ug.y, pb.y, ag1);
                ao1 = fma2(uo.x, pb.x, ao1); ao1 = fma2(uo.y, pb.y, ao1);
            }
            #pragma unroll
            for (int k = 0; k < 8; ++k) {
                ulonglong2 qa = Qa[k], qb = Qb[k];
                ulonglong2 vi = Vi[k], vf = Vf[k], vg = Vg[k], vo = Vo[k];
                ai0 = fma2(vi.x, qa.x, ai0); ai0 = fma2(vi.y, qa.y, ai0);
                af0 = fma2(vf.x, qa.x, af0); af0 = fma2(vf.y, qa.y, af0);
                ag0 = fma2(vg.x, qa.x, ag0); ag0 = fma2(vg.y, qa.y, ag0);
                ao0 = fma2(vo.x, qa.x, ao0); ao0 = fma2(vo.y, qa.y, ao0);
                ai1 = fma2(vi.x, qb.x, ai1); ai1 = fma2(vi.y, qb.y, ai1);
                af1 = fma2(vf.x, qb.x, af1); af1 = fma2(vf.y, qb.y, af1);
                ag1 = fma2(vg.x, qb.x, ag1); ag1 = fma2(vg.y, qb.y, ag1);
                ao1 = fma2(vo.x, qb.x, ao1); ao1 = fma2(vo.y, qb.y, ao1);
            }
            float ti0 = red2(ai0); ti0 += __shfl_xor_sync(~0u, ti0, 1);
            float tf0 = red2(af0); tf0 += __shfl_xor_sync(~0u, tf0, 1);
            float tg0 = red2(ag0); tg0 += __shfl_xor_sync(~0u, tg0, 1);
            float to0 = red2(ao0); to0 += __shfl_xor_sync(~0u, to0, 1);
            float ti1 = red2(ai1); ti1 += __shfl_xor_sync(~0u, ti1, 1);
            float tf1 = red2(af1); tf1 += __shfl_xor_sync(~0u, tf1, 1);
            float tg1 = red2(ag1); tg1 += __shfl_xor_sync(~0u, tg1, 1);
            float to1 = red2(ao1); to1 += __shfl_xor_sync(~0u, to1, 1);

            float gi = b2i + (kh ? ti1 : ti0);
            float gf = b2f + (kh ? tf1 : tf0);
            float gg = b2g + (kh ? tg1 : tg0);
            float go = b2o + (kh ? to1 : to0);
            float ii = sigm(gi), ff = sigm(gf), gc = tanh_(gg), oo = sigm(go);
            c2 = ff * c2 + ii * gc;
            sH2[q * HB + rsel * HP + np] = oo * tanh_(c2);
        }
        __syncthreads();   // h2[q] published

        // ====== output: warp w (w<8) reduces row w of h2[q] against w_lin ======
        if (wid < RPC) {
            const float* hr = sH2 + q * HB + wid * HP;
            float v = hr[lid] * sWl[lid] + hr[KHOFF + lid] * sWl[lid + 32];
            #pragma unroll
            for (int off = 16; off; off >>= 1)
                v += __shfl_xor_sync(0xffffffffu, v, off);
            if (lid == 0) out[(rowbase + wid) * T_LEN + t] = v + blin;
        }
    }
}

extern "C" void kernel_launch(void* const* d_in, const int* in_sizes, int n_in,
                              void* d_out, int out_size)
{
    const float* x     = (const float*)d_in[0];
    const float* w_ih1 = (const float*)d_in[1];
    const float* w_hh1 = (const float*)d_in[2];
    const float* b_ih1 = (const float*)d_in[3];
    const float* b_hh1 = (const float*)d_in[4];
    const float* w_ih2 = (const float*)d_in[5];
    const float* w_hh2 = (const float*)d_in[6];
    const float* b_ih2 = (const float*)d_in[7];
    const float* b_hh2 = (const float*)d_in[8];
    const float* w_lin = (const float*)d_in[9];
    const float* b_lin = (const float*)d_in[10];

    cudaFuncSetAttribute(lstm2_kernel,
                         cudaFuncAttributeMaxDynamicSharedMemorySize, SMEM_BYTES);

    lstm2_kernel<<<GRID, NTH, SMEM_BYTES>>>(
        x, w_ih1, w_hh1, b_ih1, b_hh1,
        w_ih2, w_hh2, b_ih2, b_hh2,
        w_lin, b_lin, (float*)d_out);
}

// round 7
// speedup vs baseline: 1.2673x; 1.2673x over previous
#include <cuda_runtime.h>

// LSTM2: 2-layer LSTM, B=1024, T=1024, H=64, input dim 1, output 1/step.
// Persistent-RNN: 128 CTAs x 256 threads, 8 batch rows per CTA.
// Thread = (hidden unit n, row-group rg of 4 rows, k-half kh).
// Each thread accumulates 4 gates x 4 rows over its 32-element k-half with
// f32x2 FMAs (weights amortized over 4 rows -> 33% fewer LDS than R=2),
// a 1-shfl butterfly merges k-halves (only the needed partials exchanged),
// lane kh activates rows {4rg+kh, 4rg+2+kh} (cell state in registers).
// Activations use tanh.approx.f32 (sigmoid via 0.5*tanh(0.5x)+0.5).

namespace {

constexpr int T_LEN = 1024;
constexpr int BATCH = 1024;
constexpr int RPC   = 8;             // batch rows per CTA
constexpr int NTH   = 256;           // threads per CTA
constexpr int GRID  = BATCH / RPC;   // 128

constexpr int WP    = 72;            // weight row pitch (floats)
constexpr int HP    = 76;            // h row pitch (floats)
constexpr int KHOFF = 36;            // offset of k-half 1 within a row
constexpr int HB    = RPC * HP;      // 608 floats per h buffer

constexpr int SMEM_FLOATS = 3 * 256 * WP + 64 + 4 * HB + 16;
constexpr int SMEM_BYTES  = SMEM_FLOATS * 4;   // 231232 B

typedef unsigned long long u64;

__device__ __forceinline__ u64 fma2(u64 a, u64 b, u64 c) {
    u64 d;
    asm("fma.rn.f32x2 %0, %1, %2, %3;" : "=l"(d) : "l"(a), "l"(b), "l"(c));
    return d;
}
__device__ __forceinline__ float red2(u64 a) {
    return __uint_as_float((unsigned)a) + __uint_as_float((unsigned)(a >> 32));
}
__device__ __forceinline__ float tanh_f(float v) {
    float r;
    asm("tanh.approx.f32 %0, %1;" : "=f"(r) : "f"(v));
    return r;
}
__device__ __forceinline__ float sigm(float v) {
    return fmaf(tanh_f(0.5f * v), 0.5f, 0.5f);
}
__device__ __forceinline__ int hpos(int k) { return (k >> 5) * KHOFF + (k & 31); }

} // namespace

__global__ void __launch_bounds__(NTH, 1)
lstm2_kernel(const float* __restrict__ x,
             const float* __restrict__ w_ih1, const float* __restrict__ w_hh1,
             const float* __restrict__ b_ih1, const float* __restrict__ b_hh1,
             const float* __restrict__ w_ih2, const float* __restrict__ w_hh2,
             const float* __restrict__ b_ih2, const float* __restrict__ b_hh2,
             const float* __restrict__ w_lin, const float* __restrict__ b_lin,
             float* __restrict__ out)
{
    extern __shared__ float sm[];
    float* sWh1 = sm;                    // [256][72]
    float* sWi2 = sWh1 + 256 * WP;       // [256][72]
    float* sWh2 = sWi2 + 256 * WP;       // [256][72]
    float* sWl  = sWh2 + 256 * WP;       // [64]
    float* sH1  = sWl + 64;              // [2][8][76]
    float* sH2  = sH1 + 2 * HB;          // [2][8][76]
    float* sX   = sH2 + 2 * HB;          // [2][8]

    const int tid = threadIdx.x;
    const int rowbase = blockIdx.x * RPC;

    // ---- load weights into padded SMEM ----
    for (int i = tid; i < 256 * 64; i += NTH) {
        int j = i >> 6, k = i & 63;
        int off = j * WP + hpos(k);
        sWh1[off] = w_hh1[i];
        sWi2[off] = w_ih2[i];
        sWh2[off] = w_hh2[i];
    }
    if (tid < 64) sWl[tid] = w_lin[tid];
    for (int i = tid; i < 4 * HB; i += NTH) sH1[i] = 0.f;   // zeros h1 AND h2
    if (tid < RPC) sX[tid] = x[(rowbase + tid) * T_LEN];
    __syncthreads();

    // thread mapping
    const int kh = tid & 1;            // k-half
    const int rg = (tid >> 1) & 1;     // row group (rows 4rg..4rg+3)
    const int n  = tid >> 2;           // hidden unit (0..63)
    const int r0 = rg * 4;
    const int rA = r0 + kh;            // activation rows for this lane
    const int rB = r0 + 2 + kh;
    const int wid = tid >> 5, lid = tid & 31;
    const int khoff = kh * KHOFF;
    const int np = hpos(n);

    // per-thread constants from GMEM (once)
    const float b1i = b_ih1[n]       + b_hh1[n];
    const float b1f = b_ih1[n + 64]  + b_hh1[n + 64];
    const float b1g = b_ih1[n + 128] + b_hh1[n + 128];
    const float b1o = b_ih1[n + 192] + b_hh1[n + 192];
    const float b2i = b_ih2[n]       + b_hh2[n];
    const float b2f = b_ih2[n + 64]  + b_hh2[n + 64];
    const float b2g = b_ih2[n + 128] + b_hh2[n + 128];
    const float b2o = b_ih2[n + 192] + b_hh2[n + 192];
    const float wxi = w_ih1[n],       wxf = w_ih1[n + 64];
    const float wxg = w_ih1[n + 128], wxo = w_ih1[n + 192];
    const float blin = b_lin[0];

    // weight row pointers (this thread's k-half)
    const ulonglong2* Wi = (const ulonglong2*)(sWh1 + n * WP + khoff);
    const ulonglong2* Wf = (const ulonglong2*)(sWh1 + (n + 64) * WP + khoff);
    const ulonglong2* Wg = (const ulonglong2*)(sWh1 + (n + 128) * WP + khoff);
    const ulonglong2* Wo = (const ulonglong2*)(sWh1 + (n + 192) * WP + khoff);
    const ulonglong2* Ui = (const ulonglong2*)(sWi2 + n * WP + khoff);
    const ulonglong2* Uf = (const ulonglong2*)(sWi2 + (n + 64) * WP + khoff);
    const ulonglong2* Ug = (const ulonglong2*)(sWi2 + (n + 128) * WP + khoff);
    const ulonglong2* Uo = (const ulonglong2*)(sWi2 + (n + 192) * WP + khoff);
    const ulonglong2* Vi = (const ulonglong2*)(sWh2 + n * WP + khoff);
    const ulonglong2* Vf = (const ulonglong2*)(sWh2 + (n + 64) * WP + khoff);
    const ulonglong2* Vg = (const ulonglong2*)(sWh2 + (n + 128) * WP + khoff);
    const ulonglong2* Vo = (const ulonglong2*)(sWh2 + (n + 192) * WP + khoff);

    // persistent cell state (this lane's two rows)
    float c1a = 0.f, c1b = 0.f, c2a = 0.f, c2b = 0.f;

    for (int t = 0; t < T_LEN; ++t) {
        const int p = t & 1, q = p ^ 1;

        // prefetch next x (hidden under compute)
        float xn = 0.f;
        if (tid < RPC) {
            int tn = (t + 1 < T_LEN) ? (t + 1) : t;
            xn = x[(rowbase + tid) * T_LEN + tn];
        }

        float h1A, h1B;
        // ============ layer 1: 4 gates x 4 rows over this k-half ============
        {
            const ulonglong2* H0 = (const ulonglong2*)(sH1 + p * HB + (r0 + 0) * HP + khoff);
            const ulonglong2* H1 = (const ulonglong2*)(sH1 + p * HB + (r0 + 1) * HP + khoff);
            const ulonglong2* H2 = (const ulonglong2*)(sH1 + p * HB + (r0 + 2) * HP + khoff);
            const ulonglong2* H3 = (const ulonglong2*)(sH1 + p * HB + (r0 + 3) * HP + khoff);
            u64 ai0=0, ai1=0, ai2=0, ai3=0;
            u64 af0=0, af1=0, af2=0, af3=0;
            u64 ag0=0, ag1=0, ag2=0, ag3=0;
            u64 ao0=0, ao1=0, ao2=0, ao3=0;
            #pragma unroll
            for (int k = 0; k < 8; ++k) {
                ulonglong2 h0 = H0[k], h1 = H1[k], h2 = H2[k], h3 = H3[k];
                ulonglong2 wi = Wi[k], wf = Wf[k], wg = Wg[k], wo = Wo[k];
                ai0 = fma2(wi.x, h0.x, ai0); ai0 = fma2(wi.y, h0.y, ai0);
                ai1 = fma2(wi.x, h1.x, ai1); ai1 = fma2(wi.y, h1.y, ai1);
                ai2 = fma2(wi.x, h2.x, ai2); ai2 = fma2(wi.y, h2.y, ai2);
                ai3 = fma2(wi.x, h3.x, ai3); ai3 = fma2(wi.y, h3.y, ai3);
                af0 = fma2(wf.x, h0.x, af0); af0 = fma2(wf.y, h0.y, af0);
                af1 = fma2(wf.x, h1.x, af1); af1 = fma2(wf.y, h1.y, af1);
                af2 = fma2(wf.x, h2.x, af2); af2 = fma2(wf.y, h2.y, af2);
                af3 = fma2(wf.x, h3.x, af3); af3 = fma2(wf.y, h3.y, af3);
                ag0 = fma2(wg.x, h0.x, ag0); ag0 = fma2(wg.y, h0.y, ag0);
                ag1 = fma2(wg.x, h1.x, ag1); ag1 = fma2(wg.y, h1.y, ag1);
                ag2 = fma2(wg.x, h2.x, ag2); ag2 = fma2(wg.y, h2.y, ag2);
                ag3 = fma2(wg.x, h3.x, ag3); ag3 = fma2(wg.y, h3.y, ag3);
                ao0 = fma2(wo.x, h0.x, ao0); ao0 = fma2(wo.y, h0.y, ao0);
                ao1 = fma2(wo.x, h1.x, ao1); ao1 = fma2(wo.y, h1.y, ao1);
                ao2 = fma2(wo.x, h2.x, ao2); ao2 = fma2(wo.y, h2.y, ao2);
                ao3 = fma2(wo.x, h3.x, ao3); ao3 = fma2(wo.y, h3.y, ao3);
            }
            float pi0 = red2(ai0), pi1 = red2(ai1), pi2 = red2(ai2), pi3 = red2(ai3);
            float pf0 = red2(af0), pf1 = red2(af1), pf2 = red2(af2), pf3 = red2(af3);
            float pg0 = red2(ag0), pg1 = red2(ag1), pg2 = red2(ag2), pg3 = red2(ag3);
            float po0 = red2(ao0), po1 = red2(ao1), po2 = red2(ao2), po3 = red2(ao3);
            // exchange only the partials the partner lane needs (1 shfl per sum)
            float siA = kh ? pi0 : pi1, siB = kh ? pi2 : pi3;
            float sfA = kh ? pf0 : pf1, sfB = kh ? pf2 : pf3;
            float sgA = kh ? pg0 : pg1, sgB = kh ? pg2 : pg3;
            float soA = kh ? po0 : po1, soB = kh ? po2 : po3;
            float iA = (kh ? pi1 : pi0) + __shfl_xor_sync(~0u, siA, 1);
            float iB = (kh ? pi3 : pi2) + __shfl_xor_sync(~0u, siB, 1);
            float fA = (kh ? pf1 : pf0) + __shfl_xor_sync(~0u, sfA, 1);
            float fB = (kh ? pf3 : pf2) + __shfl_xor_sync(~0u, sfB, 1);
            float gA = (kh ? pg1 : pg0) + __shfl_xor_sync(~0u, sgA, 1);
            float gB = (kh ? pg3 : pg2) + __shfl_xor_sync(~0u, sgB, 1);
            float oA = (kh ? po1 : po0) + __shfl_xor_sync(~0u, soA, 1);
            float oB = (kh ? po3 : po2) + __shfl_xor_sync(~0u, soB, 1);

            const float xsA = sX[p * RPC + rA];
            const float xsB = sX[p * RPC + rB];
            float ii = sigm(fmaf(wxi, xsA, b1i) + iA);
            float ff = sigm(fmaf(wxf, xsA, b1f) + fA);
            float gc = tanh_f(fmaf(wxg, xsA, b1g) + gA);
            float oo = sigm(fmaf(wxo, xsA, b1o) + oA);
            c1a = ff * c1a + ii * gc;
            h1A = oo * tanh_f(c1a);
            ii = sigm(fmaf(wxi, xsB, b1i) + iB);
            ff = sigm(fmaf(wxf, xsB, b1f) + fB);
            gc = tanh_f(fmaf(wxg, xsB, b1g) + gB);
            oo = sigm(fmaf(wxo, xsB, b1o) + oB);
            c1b = ff * c1b + ii * gc;
            h1B = oo * tanh_f(c1b);

            sH1[q * HB + rA * HP + np] = h1A;
            sH1[q * HB + rB * HP + np] = h1B;
        }
        if (tid < RPC) sX[q * RPC + tid] = xn;
        __syncthreads();   // h1[q] + x[q] published

        // ============ layer 2: U*h1[q] + V*h2[p] ============
        {
            u64 ai0=0, ai1=0, ai2=0, ai3=0;
            u64 af0=0, af1=0, af2=0, af3=0;
            u64 ag0=0, ag1=0, ag2=0, ag3=0;
            u64 ao0=0, ao1=0, ao2=0, ao3=0;
            {
                const ulonglong2* P0 = (const ulonglong2*)(sH1 + q * HB + (r0 + 0) * HP + khoff);
                const ulonglong2* P1 = (const ulonglong2*)(sH1 + q * HB + (r0 + 1) * HP + khoff);
                const ulonglong2* P2 = (const ulonglong2*)(sH1 + q * HB + (r0 + 2) * HP + khoff);
                const ulonglong2* P3 = (const ulonglong2*)(sH1 + q * HB + (r0 + 3) * HP + khoff);
                #pragma unroll
                for (int k = 0; k < 8; ++k) {
                    ulonglong2 h0 = P0[k], h1 = P1[k], h2 = P2[k], h3 = P3[k];
                    ulonglong2 wi = Ui[k], wf = Uf[k], wg = Ug[k], wo = Uo[k];
                    ai0 = fma2(wi.x, h0.x, ai0); ai0 = fma2(wi.y, h0.y, ai0);
                    ai1 = fma2(wi.x, h1.x, ai1); ai1 = fma2(wi.y, h1.y, ai1);
                    ai2 = fma2(wi.x, h2.x, ai2); ai2 = fma2(wi.y, h2.y, ai2);
                    ai3 = fma2(wi.x, h3.x, ai3); ai3 = fma2(wi.y, h3.y, ai3);
                    af0 = fma2(wf.x, h0.x, af0); af0 = fma2(wf.y, h0.y, af0);
                    af1 = fma2(wf.x, h1.x, af1); af1 = fma2(wf.y, h1.y, af1);
                    af2 = fma2(wf.x, h2.x, af2); af2 = fma2(wf.y, h2.y, af2);
                    af3 = fma2(wf.x, h3.x, af3); af3 = fma2(wf.y, h3.y, af3);
                    ag0 = fma2(wg.x, h0.x, ag0); ag0 = fma2(wg.y, h0.y, ag0);
                    ag1 = fma2(wg.x, h1.x, ag1); ag1 = fma2(wg.y, h1.y, ag1);
                    ag2 = fma2(wg.x, h2.x, ag2); ag2 = fma2(wg.y, h2.y, ag2);
                    ag3 = fma2(wg.x, h3.x, ag3); ag3 = fma2(wg.y, h3.y, ag3);
                    ao0 = fma2(wo.x, h0.x, ao0); ao0 = fma2(wo.y, h0.y, ao0);
                    ao1 = fma2(wo.x, h1.x, ao1); ao1 = fma2(wo.y, h1.y, ao1);
                    ao2 = fma2(wo.x, h2.x, ao2); ao2 = fma2(wo.y, h2.y, ao2);
                    ao3 = fma2(wo.x, h3.x, ao3); ao3 = fma2(wo.y, h3.y, ao3);
                }
            }
            {
                const ulonglong2* Q0 = (const ulonglong2*)(sH2 + p * HB + (r0 + 0) * HP + khoff);
                const ulonglong2* Q1 = (const ulonglong2*)(sH2 + p * HB + (r0 + 1) * HP + khoff);
                const ulonglong2* Q2 = (const ulonglong2*)(sH2 + p * HB + (r0 + 2) * HP + khoff);
                const ulonglong2* Q3 = (const ulonglong2*)(sH2 + p * HB + (r0 + 3) * HP + khoff);
                #pragma unroll
                for (int k = 0; k < 8; ++k) {
                    ulonglong2 h0 = Q0[k], h1 = Q1[k], h2 = Q2[k], h3 = Q3[k];
                    ulonglong2 wi = Vi[k], wf = Vf[k], wg = Vg[k], wo = Vo[k];
                    ai0 = fma2(wi.x, h0.x, ai0); ai0 = fma2(wi.y, h0.y, ai0);
                    ai1 = fma2(wi.x, h1.x, ai1); ai1 = fma2(wi.y, h1.y, ai1);
                    ai2 = fma2(wi.x, h2.x, ai2); ai2 = fma2(wi.y, h2.y, ai2);
                    ai3 = fma2(wi.x, h3.x, ai3); ai3 = fma2(wi.y, h3.y, ai3);
                    af0 = fma2(wf.x, h0.x, af0); af0 = fma2(wf.y, h0.y, af0);
                    af1 = fma2(wf.x, h1.x, af1); af1 = fma2(wf.y, h1.y, af1);
                    af2 = fma2(wf.x, h2.x, af2); af2 = fma2(wf.y, h2.y, af2);
                    af3 = fma2(wf.x, h3.x, af3); af3 = fma2(wf.y, h3.y, af3);
                    ag0 = fma2(wg.x, h0.x, ag0); ag0 = fma2(wg.y, h0.y, ag0);
                    ag1 = fma2(wg.x, h1.x, ag1); ag1 = fma2(wg.y, h1.y, ag1);
                    ag2 = fma2(wg.x, h2.x, ag2); ag2 = fma2(wg.y, h2.y, ag2);
                    ag3 = fma2(wg.x, h3.x, ag3); ag3 = fma2(wg.y, h3.y, ag3);
                    ao0 = fma2(wo.x, h0.x, ao0); ao0 = fma2(wo.y, h0.y, ao0);
                    ao1 = fma2(wo.x, h1.x, ao1); ao1 = fma2(wo.y, h1.y, ao1);
                    ao2 = fma2(wo.x, h2.x, ao2); ao2 = fma2(wo.y, h2.y, ao2);
                    ao3 = fma2(wo.x, h3.x, ao3); ao3 = fma2(wo.y, h3.y, ao3);
                }
            }
            float pi0 = red2(ai0), pi1 = red2(ai1), pi2 = red2(ai2), pi3 = red2(ai3);
            float pf0 = red2(af0), pf1 = red2(af1), pf2 = red2(af2), pf3 = red2(af3);
            float pg0 = red2(ag0), pg1 = red2(ag1), pg2 = red2(ag2), pg3 = red2(ag3);
            float po0 = red2(ao0), po1 = red2(ao1), po2 = red2(ao2), po3 = red2(ao3);
            float siA = kh ? pi0 : pi1, siB = kh ? pi2 : pi3;
            float sfA = kh ? pf0 : pf1, sfB = kh ? pf2 : pf3;
            float sgA = kh ? pg0 : pg1, sgB = kh ? pg2 : pg3;
            float soA = kh ? po0 : po1, soB = kh ? po2 : po3;
            float iA = (kh ? pi1 : pi0) + __shfl_xor_sync(~0u, siA, 1);
            float iB = (kh ? pi3 : pi2) + __shfl_xor_sync(~0u, siB, 1);
            float fA = (kh ? pf1 : pf0) + __shfl_xor_sync(~0u, sfA, 1);
            float fB = (kh ? pf3 : pf2) + __shfl_xor_sync(~0u, sfB, 1);
            float gA = (kh ? pg1 : pg0) + __shfl_xor_sync(~0u, sgA, 1);
            float gB = (kh ? pg3 : pg2) + __shfl_xor_sync(~0u, sgB, 1);
            float oA = (kh ? po1 : po0) + __shfl_xor_sync(~0u, soA, 1);
            float oB = (kh ? po3 : po2) + __shfl_xor_sync(~0u, soB, 1);

            float ii = sigm(b2i + iA);
            float ff = sigm(b2f + fA);
            float gc = tanh_f(b2g + gA);
            float oo = sigm(b2o + oA);
            c2a = ff * c2a + ii * gc;
            sH2[q * HB + rA * HP + np] = oo * tanh_f(c2a);
            ii = sigm(b2i + iB);
            ff = sigm(b2f + fB);
            gc = tanh_f(b2g + gB);
            oo = sigm(b2o + oB);
            c2b = ff * c2b + ii * gc;
            sH2[q * HB + rB * HP + np] = oo * tanh_f(c2b);
        }
        __syncthreads();   // h2[q] published

        // ====== output: warp w reduces row w of h2[q] against w_lin ======
        {
            const float* hr = sH2 + q * HB + wid * HP;
            float v = hr[lid] * sWl[lid] + hr[KHOFF + lid] * sWl[lid + 32];
            #pragma unroll
            for (int off = 16; off; off >>= 1)
                v += __shfl_xor_sync(0xffffffffu, v, off);
            if (lid == 0) out[(rowbase + wid) * T_LEN + t] = v + blin;
        }
    }
}

extern "C" void kernel_launch(void* const* d_in, const int* in_sizes, int n_in,
                              void* d_out, int out_size)
{
    const float* x     = (const float*)d_in[0];
    const float* w_ih1 = (const float*)d_in[1];
    const float* w_hh1 = (const float*)d_in[2];
    const float* b_ih1 = (const float*)d_in[3];
    const float* b_hh1 = (const float*)d_in[4];
    const float* w_ih2 = (const float*)d_in[5];
    const float* w_hh2 = (const float*)d_in[6];
    const float* b_ih2 = (const float*)d_in[7];
    const float* b_hh2 = (const float*)d_in[8];
    const float* w_lin = (const float*)d_in[9];
    const float* b_lin = (const float*)d_in[10];

    cudaFuncSetAttribute(lstm2_kernel,
                         cudaFuncAttributeMaxDynamicSharedMemorySize, SMEM_BYTES);

    lstm2_kernel<<<GRID, NTH, SMEM_BYTES>>>(
        x, w_ih1, w_hh1, b_ih1, b_hh1,
        w_ih2, w_hh2, b_ih2, b_hh2,
        w_lin, b_lin, (float*)d_out);
}

// round 8
// speedup vs baseline: 1.2887x; 1.0169x over previous
#include <cuda_runtime.h>

// LSTM2: 2-layer LSTM, B=1024, T=1024, H=64, input dim 1, output 1/step.
// Persistent-RNN: 128 CTAs x 256 threads, 8 batch rows per CTA.
// Thread = (hidden unit n, k-quarter kq). Each thread accumulates all 4 gates
// of unit n for ALL 8 rows over its 16-element k-quarter (f32x2 FMAs; weights
// amortized over 8 rows). A 2-level shfl butterfly (xor 16, xor 8) merges the
// 4 k-quarters; lane kq finalizes rows {kq, kq+4} (cell state in registers).
// Lane mapping: lane = kq*8 + n_low3 -> each LDS octet has same kq + 8
// consecutive n: weight loads conflict-free at pitch 68, h loads are pure
// octet broadcasts at pitch 72, h stores conflict-free.

namespace {

constexpr int T_LEN = 1024;
constexpr int RPC   = 8;             // batch rows per CTA
constexpr int NTH   = 256;           // threads per CTA
constexpr int GRID  = 1024 / RPC;    // 128

constexpr int WP    = 68;            // weight row pitch (floats)
constexpr int HP    = 72;            // h row pitch (floats)
constexpr int HB    = RPC * HP;      // 576 floats per h buffer

constexpr int SMEM_FLOATS = 3 * 256 * WP + 64 + 4 * HB + 16;
constexpr int SMEM_BYTES  = SMEM_FLOATS * 4;   // 218432 B

typedef unsigned long long u64;

__device__ __forceinline__ u64 fma2(u64 a, u64 b, u64 c) {
    u64 d;
    asm("fma.rn.f32x2 %0, %1, %2, %3;" : "=l"(d) : "l"(a), "l"(b), "l"(c));
    return d;
}
__device__ __forceinline__ float red2(u64 a) {
    return __uint_as_float((unsigned)a) + __uint_as_float((unsigned)(a >> 32));
}
__device__ __forceinline__ float tanh_f(float v) {
    float r;
    asm("tanh.approx.f32 %0, %1;" : "=f"(r) : "f"(v));
    return r;
}
__device__ __forceinline__ float sigm(float v) {
    return fmaf(tanh_f(0.5f * v), 0.5f, 0.5f);
}
__device__ __forceinline__ ulonglong2 ld2(const float* p) {
    return *(const ulonglong2*)p;
}

} // namespace

__global__ void __launch_bounds__(NTH, 1)
lstm2_kernel(const float* __restrict__ x,
             const float* __restrict__ w_ih1, const float* __restrict__ w_hh1,
             const float* __restrict__ b_ih1, const float* __restrict__ b_hh1,
             const float* __restrict__ w_ih2, const float* __restrict__ w_hh2,
             const float* __restrict__ b_ih2, const float* __restrict__ b_hh2,
             const float* __restrict__ w_lin, const float* __restrict__ b_lin,
             float* __restrict__ out)
{
    extern __shared__ float sm[];
    float* sWh1 = sm;                    // [256][68]
    float* sWi2 = sWh1 + 256 * WP;       // [256][68]
    float* sWh2 = sWi2 + 256 * WP;       // [256][68]
    float* sWl  = sWh2 + 256 * WP;       // [64]
    float* sH1  = sWl + 64;              // [2][8][72]
    float* sH2  = sH1 + 2 * HB;          // [2][8][72]
    float* sX   = sH2 + 2 * HB;          // [2][8]

    const int tid = threadIdx.x;
    const int rowbase = blockIdx.x * RPC;

    // ---- load weights into padded SMEM ----
    for (int i = tid; i < 256 * 64; i += NTH) {
        int j = i >> 6, k = i & 63;
        int off = j * WP + k;
        sWh1[off] = w_hh1[i];
        sWi2[off] = w_ih2[i];
        sWh2[off] = w_hh2[i];
    }
    if (tid < 64) sWl[tid] = w_lin[tid];
    for (int i = tid; i < 4 * HB; i += NTH) sH1[i] = 0.f;   // zeros h1 AND h2
    if (tid < RPC) sX[tid] = x[(rowbase + tid) * T_LEN];
    __syncthreads();

    // thread mapping: lane = kq*8 + nl; n = wid*8 + nl
    const int lid = tid & 31;
    const int wid = tid >> 5;
    const int kq  = lid >> 3;            // k-quarter 0..3
    const int n   = (wid << 3) | (lid & 7);
    const int kq16 = kq * 16;
    const int rA = kq, rB = kq + 4;      // rows this lane finalizes
    const int hi2 = kq & 2, hi1 = kq & 1;

    // per-thread constants from GMEM (once)
    const float b1i = b_ih1[n]       + b_hh1[n];
    const float b1f = b_ih1[n + 64]  + b_hh1[n + 64];
    const float b1g = b_ih1[n + 128] + b_hh1[n + 128];
    const float b1o = b_ih1[n + 192] + b_hh1[n + 192];
    const float b2i = b_ih2[n]       + b_hh2[n];
    const float b2f = b_ih2[n + 64]  + b_hh2[n + 64];
    const float b2g = b_ih2[n + 128] + b_hh2[n + 128];
    const float b2o = b_ih2[n + 192] + b_hh2[n + 192];
    const float wxi = w_ih1[n],       wxf = w_ih1[n + 64];
    const float wxg = w_ih1[n + 128], wxo = w_ih1[n + 192];
    const float blin = b_lin[0];

    // weight quarter base pointers (float*, this thread's k-quarter)
    const float* W1[4] = { sWh1 + n * WP + kq16,          sWh1 + (n + 64) * WP + kq16,
                           sWh1 + (n + 128) * WP + kq16,  sWh1 + (n + 192) * WP + kq16 };
    const float* W2[4] = { sWi2 + n * WP + kq16,          sWi2 + (n + 64) * WP + kq16,
                           sWi2 + (n + 128) * WP + kq16,  sWi2 + (n + 192) * WP + kq16 };
    const float* W3[4] = { sWh2 + n * WP + kq16,          sWh2 + (n + 64) * WP + kq16,
                           sWh2 + (n + 128) * WP + kq16,  sWh2 + (n + 192) * WP + kq16 };

    // persistent cell state (this lane's two rows)
    float c1a = 0.f, c1b = 0.f, c2a = 0.f, c2b = 0.f;

    for (int t = 0; t < T_LEN; ++t) {
        const int p = t & 1, q = p ^ 1;

        // prefetch next x (hidden under compute)
        float xn = 0.f;
        if (tid < RPC) {
            int tn = (t + 1 < T_LEN) ? (t + 1) : t;
            xn = x[(rowbase + tid) * T_LEN + tn];
        }

        // ============ layer 1: 4 gates x 8 rows over this k-quarter ============
        {
            const float* hb = sH1 + p * HB + kq16;
            u64 acc[4][8] = {};
            #pragma unroll
            for (int i = 0; i < 4; ++i) {
                const int io = i * 4;
                ulonglong2 wv0 = ld2(W1[0] + io), wv1 = ld2(W1[1] + io);
                ulonglong2 wv2 = ld2(W1[2] + io), wv3 = ld2(W1[3] + io);
                #pragma unroll
                for (int r = 0; r < 8; ++r) {
                    ulonglong2 hv = ld2(hb + r * HP + io);
                    acc[0][r] = fma2(wv0.x, hv.x, acc[0][r]);
                    acc[0][r] = fma2(wv0.y, hv.y, acc[0][r]);
                    acc[1][r] = fma2(wv1.x, hv.x, acc[1][r]);
                    acc[1][r] = fma2(wv1.y, hv.y, acc[1][r]);
                    acc[2][r] = fma2(wv2.x, hv.x, acc[2][r]);
                    acc[2][r] = fma2(wv2.y, hv.y, acc[2][r]);
                    acc[3][r] = fma2(wv3.x, hv.x, acc[3][r]);
                    acc[3][r] = fma2(wv3.y, hv.y, acc[3][r]);
                }
            }
            // 2-level butterfly per gate: lane kq ends with rows {kq, kq+4}
            float vA[4], vB[4];
            #pragma unroll
            for (int g = 0; g < 4; ++g) {
                float p0 = red2(acc[g][0]), p1 = red2(acc[g][1]);
                float p2 = red2(acc[g][2]), p3 = red2(acc[g][3]);
                float p4 = red2(acc[g][4]), p5 = red2(acc[g][5]);
                float p6 = red2(acc[g][6]), p7 = red2(acc[g][7]);
                // level 1: xor 16 (flip kq bit1); keep rows with bit1 == hi2
                float va0 = (hi2 ? p2 : p0) + __shfl_xor_sync(~0u, hi2 ? p0 : p2, 16);
                float va1 = (hi2 ? p3 : p1) + __shfl_xor_sync(~0u, hi2 ? p1 : p3, 16);
                float va4 = (hi2 ? p6 : p4) + __shfl_xor_sync(~0u, hi2 ? p4 : p6, 16);
                float va5 = (hi2 ? p7 : p5) + __shfl_xor_sync(~0u, hi2 ? p5 : p7, 16);
                // level 2: xor 8 (flip kq bit0); keep rows with bit0 == hi1
                vA[g] = (hi1 ? va1 : va0) + __shfl_xor_sync(~0u, hi1 ? va0 : va1, 8);
                vB[g] = (hi1 ? va5 : va4) + __shfl_xor_sync(~0u, hi1 ? va4 : va5, 8);
            }

            const float xsA = sX[p * RPC + rA];
            const float xsB = sX[p * RPC + rB];
            float ii = sigm(fmaf(wxi, xsA, b1i) + vA[0]);
            float ff = sigm(fmaf(wxf, xsA, b1f) + vA[1]);
            float gc = tanh_f(fmaf(wxg, xsA, b1g) + vA[2]);
            float oo = sigm(fmaf(wxo, xsA, b1o) + vA[3]);
            c1a = ff * c1a + ii * gc;
            sH1[q * HB + rA * HP + n] = oo * tanh_f(c1a);
            ii = sigm(fmaf(wxi, xsB, b1i) + vB[0]);
            ff = sigm(fmaf(wxf, xsB, b1f) + vB[1]);
            gc = tanh_f(fmaf(wxg, xsB, b1g) + vB[2]);
            oo = sigm(fmaf(wxo, xsB, b1o) + vB[3]);
            c1b = ff * c1b + ii * gc;
            sH1[q * HB + rB * HP + n] = oo * tanh_f(c1b);
        }
        if (tid < RPC) sX[q * RPC + tid] = xn;
        __syncthreads();   // h1[q] + x[q] published

        // ============ layer 2: U*h1[q] + V*h2[p] ============
        {
            u64 acc[4][8] = {};
            {
                const float* hb = sH1 + q * HB + kq16;
                #pragma unroll
                for (int i = 0; i < 4; ++i) {
                    const int io = i * 4;
                    ulonglong2 wv0 = ld2(W2[0] + io), wv1 = ld2(W2[1] + io);
                    ulonglong2 wv2 = ld2(W2[2] + io), wv3 = ld2(W2[3] + io);
                    #pragma unroll
                    for (int r = 0; r < 8; ++r) {
                        ulonglong2 hv = ld2(hb + r * HP + io);
                        acc[0][r] = fma2(wv0.x, hv.x, acc[0][r]);
                        acc[0][r] = fma2(wv0.y, hv.y, acc[0][r]);
                        acc[1][r] = fma2(wv1.x, hv.x, acc[1][r]);
                        acc[1][r] = fma2(wv1.y, hv.y, acc[1][r]);
                        acc[2][r] = fma2(wv2.x, hv.x, acc[2][r]);
                        acc[2][r] = fma2(wv2.y, hv.y, acc[2][r]);
                        acc[3][r] = fma2(wv3.x, hv.x, acc[3][r]);
                        acc[3][r] = fma2(wv3.y, hv.y, acc[3][r]);
                    }
                }
            }
            {
                const float* hb = sH2 + p * HB + kq16;
                #pragma unroll
                for (int i = 0; i < 4; ++i) {
                    const int io = i * 4;
                    ulonglong2 wv0 = ld2(W3[0] + io), wv1 = ld2(W3[1] + io);
                    ulonglong2 wv2 = ld2(W3[2] + io), wv3 = ld2(W3[3] + io);
                    #pragma unroll
                    for (int r = 0; r < 8; ++r) {
                        ulonglong2 hv = ld2(hb + r * HP + io);
                        acc[0][r] = fma2(wv0.x, hv.x, acc[0][r]);
                        acc[0][r] = fma2(wv0.y, hv.y, acc[0][r]);
                        acc[1][r] = fma2(wv1.x, hv.x, acc[1][r]);
                        acc[1][r] = fma2(wv1.y, hv.y, acc[1][r]);
                        acc[2][r] = fma2(wv2.x, hv.x, acc[2][r]);
                        acc[2][r] = fma2(wv2.y, hv.y, acc[2][r]);
                        acc[3][r] = fma2(wv3.x, hv.x, acc[3][r]);
                        acc[3][r] = fma2(wv3.y, hv.y, acc[3][r]);
                    }
                }
            }
            float vA[4], vB[4];
            #pragma unroll
            for (int g = 0; g < 4; ++g) {
                float p0 = red2(acc[g][0]), p1 = red2(acc[g][1]);
                float p2 = red2(acc[g][2]), p3 = red2(acc[g][3]);
                float p4 = red2(acc[g][4]), p5 = red2(acc[g][5]);
                float p6 = red2(acc[g][6]), p7 = red2(acc[g][7]);
                float va0 = (hi2 ? p2 : p0) + __shfl_xor_sync(~0u, hi2 ? p0 : p2, 16);
                float va1 = (hi2 ? p3 : p1) + __shfl_xor_sync(~0u, hi2 ? p1 : p3, 16);
                float va4 = (hi2 ? p6 : p4) + __shfl_xor_sync(~0u, hi2 ? p4 : p6, 16);
                float va5 = (hi2 ? p7 : p5) + __shfl_xor_sync(~0u, hi2 ? p5 : p7, 16);
                vA[g] = (hi1 ? va1 : va0) + __shfl_xor_sync(~0u, hi1 ? va0 : va1, 8);
                vB[g] = (hi1 ? va5 : va4) + __shfl_xor_sync(~0u, hi1 ? va4 : va5, 8);
            }

            float ii = sigm(b2i + vA[0]);
            float ff = sigm(b2f + vA[1]);
            float gc = tanh_f(b2g + vA[2]);
            float oo = sigm(b2o + vA[3]);
            c2a = ff * c2a + ii * gc;
            sH2[q * HB + rA * HP + n] = oo * tanh_f(c2a);
            ii = sigm(b2i + vB[0]);
            ff = sigm(b2f + vB[1]);
            gc = tanh_f(b2g + vB[2]);
            oo = sigm(b2o + vB[3]);
            c2b = ff * c2b + ii * gc;
            sH2[q * HB + rB * HP + n] = oo * tanh_f(c2b);
        }
        __syncthreads();   // h2[q] published

        // ====== output: warp w reduces row w of h2[q] against w_lin ======
        {
            const float* hr = sH2 + q * HB + wid * HP;
            float v = hr[lid] * sWl[lid] + hr[lid + 32] * sWl[lid + 32];
            #pragma unroll
            for (int off = 16; off; off >>= 1)
                v += __shfl_xor_sync(0xffffffffu, v, off);
            if (lid == 0) out[(rowbase + wid) * T_LEN + t] = v + blin;
        }
    }
}

extern "C" void kernel_launch(void* const* d_in, const int* in_sizes, int n_in,
                              void* d_out, int out_size)
{
    const float* x     = (const float*)d_in[0];
    const float* w_ih1 = (const float*)d_in[1];
    const float* w_hh1 = (const float*)d_in[2];
    const float* b_ih1 = (const float*)d_in[3];
    const float* b_hh1 = (const float*)d_in[4];
    const float* w_ih2 = (const float*)d_in[5];
    const float* w_hh2 = (const float*)d_in[6];
    const float* b_ih2 = (const float*)d_in[7];
    const float* b_hh2 = (const float*)d_in[8];
    const float* w_lin = (const float*)d_in[9];
    const float* b_lin = (const float*)d_in[10];

    cudaFuncSetAttribute(lstm2_kernel,
                         cudaFuncAttributeMaxDynamicSharedMemorySize, SMEM_BYTES);

    lstm2_kernel<<<GRID, NTH, SMEM_BYTES>>>(
        x, w_ih1, w_hh1, b_ih1, b_hh1,
        w_ih2, w_hh2, b_ih2, b_hh2,
        w_lin, b_lin, (float*)d_out);
}